// round 11
// baseline (speedup 1.0000x reference)
#include <cuda_runtime.h>

// CropAndResize: image (8,256,200,200) f32 NCHW, boxes (512,4) [y1,x1,y2,x2],
// box_indices (512,) int32 -> out (512,256,14,14) f32. Bilinear, extrap 0.
//
// R11: vectorized gathers. Per (box, crop-col) precompute a 5-tap weight
// vector over the 16B-aligned float4 window containing x0/x1. Per channel:
// 2x LDG.128 (+ <=2 predicated LDG.32) + 11 FMA per output. 4x bytes per
// outstanding-load slot -> enough flight bytes to saturate HBM.

#define IH 200
#define IW 200
#define CROP 14
#define NCH 256
#define NBOX 512
#define NIMG 8
#define PLANE (IH * IW)
#define POS (CROP * CROP)          // 196
#define CCHUNK 64                  // channels per block
#define NCHUNKS (NCH / CCHUNK)     // 4
#define TPB (2 * POS)              // 392: c0 = tid/196
#define CITERS (CCHUNK / 2)        // 32

__device__ int d_perm[NBOX];       // box ids sorted by image index

__global__ __launch_bounds__(NBOX) void sort_boxes_kernel(
    const int* __restrict__ box_idx)
{
    __shared__ int cnt[NIMG];
    __shared__ int off[NIMG + 1];
    const int tid = threadIdx.x;
    if (tid < NIMG) cnt[tid] = 0;
    __syncthreads();
    const int b = box_idx[tid];
    atomicAdd(&cnt[b], 1);
    __syncthreads();
    if (tid == 0) {
        int s = 0;
        for (int i = 0; i < NIMG; ++i) { off[i] = s; s += cnt[i]; }
        off[NIMG] = s;
    }
    __syncthreads();
    const int pos = atomicAdd(&off[b], 1);   // bucket-internal order irrelevant
    d_perm[pos] = tid;
}

__global__ __launch_bounds__(TPB) void crop_resize_kernel(
    const float* __restrict__ image,
    const float* __restrict__ boxes,
    const int*   __restrict__ box_idx,
    float*       __restrict__ out)
{
    __shared__ float sw[CROP][5];            // 5-tap x weights per crop-col
    __shared__ int   sa0[CROP];              // aligned window start per col
    __shared__ int   sy0[CROP], sy1[CROP];
    __shared__ float sly[CROP];
    __shared__ unsigned svx[CROP], svy[CROP];
    __shared__ int sn;
    __shared__ const float* splane;

    const int cchunk = blockIdx.x / NBOX;    // cchunk-major + sorted boxes:
    const int spos   = blockIdx.x % NBOX;    // small L2 working set
    const int tid    = threadIdx.x;

    if (tid == 0) {
        const int n = d_perm[spos];
        sn = n;
        splane = image + (size_t)box_idx[n] * NCH * PLANE;
    }
    __syncthreads();
    const int n = sn;

    // Threads 0..13: x-axis windows+weights. Threads 14..27: y-axis.
    if (tid < 2 * CROP) {
        const bool isx = (tid < CROP);
        const int  k   = isx ? tid : tid - CROP;
        const float a1 = boxes[n * 4 + (isx ? 1 : 0)];
        const float a2 = boxes[n * 4 + (isx ? 3 : 2)];
        const float D  = isx ? (float)(IW - 1) : (float)(IH - 1);
        const float scale = (a2 - a1) * D * (1.0f / (CROP - 1));
        const float v  = a1 * D + (float)k * scale;
        const unsigned valid = (v >= 0.0f) && (v <= D);
        const float fl = floorf(v);
        const float l  = v - fl;
        const int i0 = (int)fminf(fmaxf(fl, 0.0f), D);
        const int i1 = (int)fminf(fmaxf(ceilf(v), 0.0f), D);
        if (isx) {
            const int a0 = i0 & ~3;
            sa0[k] = a0;
            #pragma unroll
            for (int i = 0; i < 5; ++i) sw[k][i] = 0.0f;
            sw[k][i0 - a0] += 1.0f - l;      // i1 - a0 <= 4 since i1 <= i0+1
            sw[k][i1 - a0] += l;
            svx[k] = valid;
        } else {
            sy0[k] = i0; sy1[k] = i1; sly[k] = l; svy[k] = valid;
        }
    }
    __syncthreads();

    // Fixed per-thread decode: c0 in {0,1}, pos in [0,196)
    const int c0  = (tid >= POS) ? 1 : 0;
    const int pos = tid - c0 * POS;
    const int r   = pos / CROP;
    const int col = pos - r * CROP;

    const float w0 = sw[col][0], w1 = sw[col][1], w2 = sw[col][2],
                w3 = sw[col][3], w4 = sw[col][4];
    const int   a0 = sa0[col];
    const float ly = sly[r];
    const bool valid = (svy[r] & svx[col]) != 0;
    const bool need4 = (w4 != 0.0f);

    const float* pl = splane + (size_t)cchunk * CCHUNK * PLANE + (size_t)c0 * PLANE;
    const float* rowT = pl + sy0[r] * IW + a0;   // 16B-aligned (IW*4=800, a0%4==0)
    const float* rowB = pl + sy1[r] * IW + a0;
    float* outp = out + (size_t)n * NCH * POS + (size_t)cchunk * CCHUNK * POS
                      + (size_t)c0 * POS + pos;

    if (valid) {
        #pragma unroll 4
        for (int it = 0; it < CITERS; ++it) {
            const float4 t0 = __ldg((const float4*)rowT);
            const float4 b0 = __ldg((const float4*)rowB);
            float t4 = 0.0f, b4 = 0.0f;
            if (need4) {                       // predicated scalar loads
                t4 = __ldg(rowT + 4);
                b4 = __ldg(rowB + 4);
            }
            float top = t0.x * w0;
            top = fmaf(t0.y, w1, top);
            top = fmaf(t0.z, w2, top);
            top = fmaf(t0.w, w3, top);
            top = fmaf(t4,   w4, top);
            float bot = b0.x * w0;
            bot = fmaf(b0.y, w1, bot);
            bot = fmaf(b0.z, w2, bot);
            bot = fmaf(b0.w, w3, bot);
            bot = fmaf(b4,   w4, bot);
            const float val = fmaf(bot - top, ly, top);
            __stcs(outp, val);
            rowT += 2 * PLANE;
            rowB += 2 * PLANE;
            outp += 2 * POS;
        }
    } else {
        #pragma unroll 8
        for (int it = 0; it < CITERS; ++it) {
            __stcs(outp, 0.0f);
            outp += 2 * POS;
        }
    }
}

extern "C" void kernel_launch(void* const* d_in, const int* in_sizes, int n_in,
                              void* d_out, int out_size)
{
    const float* image   = (const float*)d_in[0];
    const float* boxes   = (const float*)d_in[1];
    const int*   box_idx = (const int*)d_in[2];
    float*       out     = (float*)d_out;

    sort_boxes_kernel<<<1, NBOX>>>(box_idx);
    crop_resize_kernel<<<NCHUNKS * NBOX, TPB>>>(image, boxes, box_idx, out);
}

// round 12
// speedup vs baseline: 1.1864x; 1.1864x over previous
#include <cuda_runtime.h>

// CropAndResize: image (8,256,200,200) f32 NCHW, boxes (512,4) [y1,x1,y2,x2],
// box_indices (512,) int32 -> out (512,256,14,14) f32. Bilinear, extrap 0.
//
// R12: best-measured skeleton (sorted boxes, cchunk-major blocks, fixed crop
// position per thread) with a 2x deeper independent-load window: 2 channels
// per iteration (8 independent LDGs per body), unroll 2 -> 16-load window.
// __launch_bounds__(392,4) keeps 4 CTAs/SM resident.

#define IH 200
#define IW 200
#define CROP 14
#define NCH 256
#define NBOX 512
#define NIMG 8
#define PLANE (IH * IW)
#define POS (CROP * CROP)          // 196
#define CCHUNK 64                  // channels per block
#define NCHUNKS (NCH / CCHUNK)     // 4
#define TPB (2 * POS)              // 392: sub = tid/196 in {0,1}
#define STRIP 32                   // channels per thread (contiguous)

__device__ int d_perm[NBOX];       // box ids sorted by image index

__global__ __launch_bounds__(NBOX) void sort_boxes_kernel(
    const int* __restrict__ box_idx)
{
    __shared__ int cnt[NIMG];
    __shared__ int off[NIMG + 1];
    const int tid = threadIdx.x;
    if (tid < NIMG) cnt[tid] = 0;
    __syncthreads();
    const int b = box_idx[tid];
    atomicAdd(&cnt[b], 1);
    __syncthreads();
    if (tid == 0) {
        int s = 0;
        for (int i = 0; i < NIMG; ++i) { off[i] = s; s += cnt[i]; }
        off[NIMG] = s;
    }
    __syncthreads();
    const int pos = atomicAdd(&off[b], 1);   // bucket-internal order irrelevant
    d_perm[pos] = tid;
}

__global__ __launch_bounds__(TPB, 4) void crop_resize_kernel(
    const float* __restrict__ image,
    const float* __restrict__ boxes,
    const int*   __restrict__ box_idx,
    float*       __restrict__ out)
{
    __shared__ int   sy0[CROP], sy1[CROP], sx0[CROP], sx1[CROP];
    __shared__ float sly[CROP], slx[CROP];
    __shared__ unsigned svy[CROP], svx[CROP];
    __shared__ int sn;
    __shared__ const float* splane;

    const int cchunk = blockIdx.x / NBOX;   // cchunk-major + sorted boxes:
    const int spos   = blockIdx.x % NBOX;   // small L2 working set
    const int tid    = threadIdx.x;

    if (tid == 0) {
        const int n = d_perm[spos];
        sn = n;
        splane = image + (size_t)box_idx[n] * NCH * PLANE;
    }
    __syncthreads();
    const int n = sn;

    // Per-box interpolation coefficients: threads 0..13 x-axis, 14..27 y-axis.
    if (tid < 2 * CROP) {
        const bool isx = (tid < CROP);
        const int  k   = isx ? tid : tid - CROP;
        const float a1 = boxes[n * 4 + (isx ? 1 : 0)];
        const float a2 = boxes[n * 4 + (isx ? 3 : 2)];
        const float D  = isx ? (float)(IW - 1) : (float)(IH - 1);
        const float scale = (a2 - a1) * D * (1.0f / (CROP - 1));
        const float v  = a1 * D + (float)k * scale;
        const unsigned valid = (v >= 0.0f) && (v <= D);
        const float fl = floorf(v);
        const float ce = ceilf(v);
        const float l  = v - fl;
        const int i0 = (int)fminf(fmaxf(fl, 0.0f), D);
        const int i1 = (int)fminf(fmaxf(ce, 0.0f), D);
        if (isx) { sx0[k] = i0; sx1[k] = i1; slx[k] = l; svx[k] = valid; }
        else     { sy0[k] = i0; sy1[k] = i1; sly[k] = l; svy[k] = valid; }
    }
    __syncthreads();

    // Fixed per-thread decode: sub in {0,1} picks a 32-channel strip.
    const int sub = (tid >= POS) ? 1 : 0;
    const int pos = tid - sub * POS;
    const int r   = pos / CROP;
    const int col = pos - r * CROP;

    const int y0 = sy0[r], y1 = sy1[r];
    const int x0 = sx0[col], x1 = sx1[col];
    const float lx = slx[col], ly = sly[r];
    const bool valid = (svy[r] & svx[col]) != 0;

    const int o_tl = y0 * IW + x0;
    const int o_tr = y0 * IW + x1;
    const int o_bl = y1 * IW + x0;
    const int o_br = y1 * IW + x1;

    const int cbase = cchunk * CCHUNK + sub * STRIP;
    const float* pl = splane + (size_t)cbase * PLANE;
    float* outp = out + (size_t)n * NCH * POS + (size_t)cbase * POS + pos;

    if (valid) {
        #pragma unroll 2
        for (int k = 0; k < STRIP; k += 2) {
            const float* p0 = pl;
            const float* p1 = pl + PLANE;
            // 8 independent loads issued back-to-back
            const float tl0 = __ldg(p0 + o_tl);
            const float tr0 = __ldg(p0 + o_tr);
            const float bl0 = __ldg(p0 + o_bl);
            const float br0 = __ldg(p0 + o_br);
            const float tl1 = __ldg(p1 + o_tl);
            const float tr1 = __ldg(p1 + o_tr);
            const float bl1 = __ldg(p1 + o_bl);
            const float br1 = __ldg(p1 + o_br);

            const float top0 = fmaf(tr0 - tl0, lx, tl0);
            const float bot0 = fmaf(br0 - bl0, lx, bl0);
            const float top1 = fmaf(tr1 - tl1, lx, tl1);
            const float bot1 = fmaf(br1 - bl1, lx, bl1);
            __stcs(outp,       fmaf(bot0 - top0, ly, top0));
            __stcs(outp + POS, fmaf(bot1 - top1, ly, top1));
            pl   += 2 * PLANE;
            outp += 2 * POS;
        }
    } else {
        #pragma unroll 8
        for (int k = 0; k < STRIP; ++k) {
            __stcs(outp, 0.0f);
            outp += POS;
        }
    }
}

extern "C" void kernel_launch(void* const* d_in, const int* in_sizes, int n_in,
                              void* d_out, int out_size)
{
    const float* image   = (const float*)d_in[0];
    const float* boxes   = (const float*)d_in[1];
    const int*   box_idx = (const int*)d_in[2];
    float*       out     = (float*)d_out;

    sort_boxes_kernel<<<1, NBOX>>>(box_idx);
    crop_resize_kernel<<<NCHUNKS * NBOX, TPB>>>(image, boxes, box_idx, out);
}